// round 3
// baseline (speedup 1.0000x reference)
#include <cuda_runtime.h>
#include <stdint.h>

#define IN_DIM 128
#define OUT_DIM 64
#define NH 4
#define DH 16
#define N_MAX 100000
#define E_MAX 1600000

// ---------------- device scratch (no allocations allowed) ----------------
__device__ float g_va[8 * IN_DIM];                    // rows 0-3: W^T a_src, 4-7: W^T a_dst
__device__ float g_h[(size_t)N_MAX * OUT_DIM];        // projected features
__device__ float g_ssrc[N_MAX * NH];                  // per-node src scores
__device__ float g_sdst[N_MAX * NH];                  // per-node dst scores
__device__ int   g_deg[N_MAX];
__device__ int   g_rowptr[N_MAX + 1];
__device__ int   g_wpos[N_MAX];
__device__ int   g_csr[E_MAX];                        // src per CSR slot
__device__ int   g_partials[128];                     // scan block partials

// ---------------- packed f32x2 helpers -----------------------------------
__device__ __forceinline__ void ffma2(uint64_t& d, uint64_t a, uint64_t b) {
    asm("fma.rn.f32x2 %0, %1, %2, %0;" : "+l"(d) : "l"(a), "l"(b));
}
__device__ __forceinline__ float2 u2f(uint64_t v) {
    float2 f;
    asm("mov.b64 {%0, %1}, %2;" : "=f"(f.x), "=f"(f.y) : "l"(v));
    return f;
}

// ---------------- fast exp on FMA pipe ------------------------------------
__device__ __forceinline__ float fast_exp(float x) {
    float t = x * 1.4426950408889634f;
    float n = rintf(t);
    float u = t - n;
    float p = 1.33335581464e-3f;
    p = fmaf(p, u, 9.61812910763e-3f);
    p = fmaf(p, u, 5.55041086648e-2f);
    p = fmaf(p, u, 2.40226506959e-1f);
    p = fmaf(p, u, 6.93147180560e-1f);
    p = fmaf(p, u, 1.0f);
    int ni = (int)n;
    return __int_as_float(__float_as_int(p) + (ni << 23));
}

// ---------------- K0: va = W^T a  (8 x 128, folds scores into GEMM) ------
__global__ void k_va(const float* __restrict__ W,
                     const float* __restrict__ a_src,
                     const float* __restrict__ a_dst) {
    int idx = blockIdx.x * blockDim.x + threadIdx.x;   // 1024 threads
    if (idx >= 8 * IN_DIM) return;
    int r = idx >> 7;          // 0..7
    int k = idx & 127;
    int hd  = r & 3;
    const float* a = (r < 4) ? a_src : a_dst;
    float s = 0.f;
#pragma unroll
    for (int d = 0; d < DH; d++)
        s = fmaf(W[(hd * DH + d) * IN_DIM + k], a[hd * DH + d], s);
    g_va[idx] = s;
}

// ---------------- K0b: zero degree histogram -----------------------------
__global__ void k_zero_deg(int n) {
    int idx = blockIdx.x * blockDim.x + threadIdx.x;
    if (idx < n) g_deg[idx] = 0;
}

// ---------------- K1: GEMM h|scores = x @ [W; va]^T  (f32x2 packed) ------
// 64 rows x 80 cols per block, 256 threads, each thread 4 rows x 5 cols
// (cols tx+16j). K paired into f32x2 lanes: acc lo=even-k, hi=odd-k,
// horizontal add in epilogue. Cols 64-71 are the fused attention scores.
__global__ __launch_bounds__(256) void k_gemm(const float* __restrict__ x,
                                              const float* __restrict__ W, int n) {
    __shared__ float xs[64 * 66];   // [m][k-chunk], pad 66 (even -> 8B align, banks 2*tx)
    __shared__ float ws[80 * 66];   // [o][k-chunk]

    int t  = threadIdx.x;
    int tx = t & 15;
    int ty = t >> 4;
    int m0 = blockIdx.x * 64;

    uint64_t acc[4][5];
#pragma unroll
    for (int i = 0; i < 4; i++)
#pragma unroll
        for (int j = 0; j < 5; j++) acc[i][j] = 0ull;

    int xbase = (ty * 4) * 66;
    int wbase = tx * 66;           // + j*16*66

    for (int kk = 0; kk < IN_DIM; kk += 64) {
        // stage x tile: 64 rows x 32 float2 (coalesced 256B per warp)
#pragma unroll
        for (int i = 0; i < 8; i++) {
            int idx = t + i * 256;
            int r = idx >> 5, c = idx & 31;
            float2 v = make_float2(0.f, 0.f);
            if (m0 + r < n)
                v = *(const float2*)&x[(size_t)(m0 + r) * IN_DIM + kk + c * 2];
            *(float2*)&xs[r * 66 + c * 2] = v;
        }
        // stage [W; va; 0] tile: 80 rows x 32 float2
#pragma unroll
        for (int i = 0; i < 10; i++) {
            int idx = t + i * 256;
            int r = idx >> 5, c = idx & 31;
            float2 v = make_float2(0.f, 0.f);
            if (r < 64)      v = *(const float2*)&W[r * IN_DIM + kk + c * 2];
            else if (r < 72) v = *(const float2*)&g_va[(r - 64) * IN_DIM + kk + c * 2];
            *(float2*)&ws[r * 66 + c * 2] = v;
        }
        __syncthreads();

#pragma unroll 8
        for (int kp = 0; kp < 32; kp++) {
            uint64_t xv[4], wv[5];
#pragma unroll
            for (int i = 0; i < 4; i++)
                xv[i] = *(const uint64_t*)&xs[xbase + i * 66 + kp * 2];
#pragma unroll
            for (int j = 0; j < 5; j++)
                wv[j] = *(const uint64_t*)&ws[wbase + j * (16 * 66) + kp * 2];
#pragma unroll
            for (int i = 0; i < 4; i++)
#pragma unroll
                for (int j = 0; j < 5; j++)
                    ffma2(acc[i][j], xv[i], wv[j]);
        }
        __syncthreads();
    }

    // epilogue: horizontal add of k-halves; write h + fused scores
#pragma unroll
    for (int i = 0; i < 4; i++) {
        int row = m0 + ty * 4 + i;
        if (row < n) {
            float* hrow = &g_h[(size_t)row * OUT_DIM];
#pragma unroll
            for (int j = 0; j < 4; j++) {
                float2 v = u2f(acc[i][j]);
                hrow[tx + 16 * j] = v.x + v.y;
            }
            float2 v4 = u2f(acc[i][4]);
            float sv = v4.x + v4.y;
            if (tx < 4)      g_ssrc[row * NH + tx]       = sv;
            else if (tx < 8) g_sdst[row * NH + (tx - 4)] = sv;
        }
    }
}

// ---------------- K3: degree histogram -----------------------------------
__global__ void k_hist(const int* __restrict__ dst, int e) {
    int idx = blockIdx.x * blockDim.x + threadIdx.x;
    if (idx < e) atomicAdd(&g_deg[dst[idx]], 1);
}

// ---------------- K4: 3-step exclusive scan of degrees -------------------
__global__ void k_scan_a(int n) {   // grid: ceil(n/1024), block 1024
    __shared__ int warp_sums[32];
    int i = blockIdx.x * 1024 + threadIdx.x;
    int lane = threadIdx.x & 31, wid = threadIdx.x >> 5;
    int v = (i < n) ? g_deg[i] : 0;
    int s = v;
#pragma unroll
    for (int o = 1; o < 32; o <<= 1) {
        int t = __shfl_up_sync(0xFFFFFFFFu, s, o);
        if (lane >= o) s += t;
    }
    if (lane == 31) warp_sums[wid] = s;
    __syncthreads();
    if (wid == 0) {
        int wsv = warp_sums[lane];
#pragma unroll
        for (int o = 1; o < 32; o <<= 1) {
            int t = __shfl_up_sync(0xFFFFFFFFu, wsv, o);
            if (lane >= o) wsv += t;
        }
        warp_sums[lane] = wsv;
    }
    __syncthreads();
    int off = wid ? warp_sums[wid - 1] : 0;
    int incl = s + off;
    if (i < n) g_rowptr[i] = incl - v;               // local exclusive
    if (threadIdx.x == 1023) g_partials[blockIdx.x] = incl;  // block total
}

__global__ void k_scan_b(int nb) {  // 1 block, 128 threads, nb <= 128
    __shared__ int sm[4];
    int t = threadIdx.x;
    int lane = t & 31, wid = t >> 5;
    int v = (t < nb) ? g_partials[t] : 0;
    int s = v;
#pragma unroll
    for (int o = 1; o < 32; o <<= 1) {
        int x = __shfl_up_sync(0xFFFFFFFFu, s, o);
        if (lane >= o) s += x;
    }
    if (lane == 31) sm[wid] = s;
    __syncthreads();
    int off = 0;
    for (int k = 0; k < wid; k++) off += sm[k];
    g_partials[t] = s + off - v;                      // exclusive
}

__global__ void k_scan_c(int n, int e) {
    int i = blockIdx.x * 1024 + threadIdx.x;
    if (i < n) {
        int r = g_rowptr[i] + g_partials[i >> 10];
        g_rowptr[i] = r;
        g_wpos[i]   = r;
    }
    if (i == 0) g_rowptr[n] = e;
}

// ---------------- K5: reorder edges into CSR (store src only) ------------
__global__ void k_reorder(const int* __restrict__ src,
                          const int* __restrict__ dst, int e) {
    int idx = blockIdx.x * blockDim.x + threadIdx.x;
    if (idx < e) {
        int d = dst[idx];
        int p = atomicAdd(&g_wpos[d], 1);
        g_csr[p] = src[idx];
    }
}

// ---------------- K6: fused softmax + weighted aggregation ---------------
// One warp per dst node, 16 lanes per edge, 2 edges in flight, CSR-index
// prefetch to break the dependent-load chain. Single write per output.
__global__ __launch_bounds__(256) void k_agg(float* __restrict__ out, int n) {
    int w = (blockIdx.x * blockDim.x + threadIdx.x) >> 5;
    if (w >= n) return;
    int lane = threadIdx.x & 31;
    int slot = lane >> 4;
    int q    = lane & 15;
    int hd   = q >> 2;

    int start = g_rowptr[w];
    int end   = g_rowptr[w + 1];
    float sdst = g_sdst[w * NH + hd];

    float4 acc = make_float4(0.f, 0.f, 0.f, 0.f);
    float ssum = 0.f;

    int j = start + slot;
    int src_cur = (j < end) ? __ldg(&g_csr[j]) : 0;
    for (; j < end; j += 2) {
        int jn = j + 2;
        int src_nxt = (jn < end) ? __ldg(&g_csr[jn]) : 0;   // prefetch
        int src = src_cur;
        float s = __ldg(&g_ssrc[src * NH + hd]) + sdst;
        float ev = (s > 0.f) ? s : 0.2f * s;       // leaky_relu(0.2)
        float p = fast_exp(ev);                    // unshifted exp: max cancels
        float4 hv = *(const float4*)&g_h[(size_t)src * OUT_DIM + q * 4];
        acc.x = fmaf(p, hv.x, acc.x);
        acc.y = fmaf(p, hv.y, acc.y);
        acc.z = fmaf(p, hv.z, acc.z);
        acc.w = fmaf(p, hv.w, acc.w);
        ssum += p;
        src_cur = src_nxt;
    }

    acc.x += __shfl_xor_sync(0xFFFFFFFFu, acc.x, 16);
    acc.y += __shfl_xor_sync(0xFFFFFFFFu, acc.y, 16);
    acc.z += __shfl_xor_sync(0xFFFFFFFFu, acc.z, 16);
    acc.w += __shfl_xor_sync(0xFFFFFFFFu, acc.w, 16);
    ssum  += __shfl_xor_sync(0xFFFFFFFFu, ssum, 16);

    if (slot == 0) {
        float inv = 1.f / fmaxf(ssum, 1e-9f);
        float4 o = make_float4(acc.x * inv, acc.y * inv, acc.z * inv, acc.w * inv);
        *(float4*)&out[(size_t)w * OUT_DIM + q * 4] = o;
    }
}

// ---------------- launch ---------------------------------------------------
extern "C" void kernel_launch(void* const* d_in, const int* in_sizes, int n_in,
                              void* d_out, int out_size) {
    const float* x     = (const float*)d_in[0];
    const float* W     = (const float*)d_in[1];
    const float* a_src = (const float*)d_in[2];
    const float* a_dst = (const float*)d_in[3];
    const int*   ei    = (const int*)d_in[4];

    int n = in_sizes[0] / IN_DIM;
    int e = in_sizes[4] / 2;
    const int* srcp = ei;
    const int* dstp = ei + e;
    float* out = (float*)d_out;

    k_va      <<<8, 128>>>(W, a_src, a_dst);
    k_zero_deg<<<(n + 255) / 256, 256>>>(n);
    k_gemm    <<<(n + 63) / 64, 256>>>(x, W, n);
    k_hist    <<<(e + 255) / 256, 256>>>(dstp, e);
    int nb = (n + 1023) / 1024;
    k_scan_a  <<<nb, 1024>>>(n);
    k_scan_b  <<<1, 128>>>(nb);
    k_scan_c  <<<nb, 1024>>>(n, e);
    k_reorder <<<(e + 255) / 256, 256>>>(srcp, dstp, e);
    k_agg     <<<(n + 7) / 8, 256>>>(out, n);
}

// round 6
// speedup vs baseline: 1.1292x; 1.1292x over previous
#include <cuda_runtime.h>
#include <stdint.h>

#define IN_DIM 128
#define OUT_DIM 64
#define NH 4
#define DH 16
#define N_MAX 100000
#define E_MAX 1600000

#define WT_COLS 80          // 64 h cols + 8 score cols + 8 zero pad
#define HIST_BLOCKS 128
#define REORD_BLOCKS 128

// ---------------- device scratch (no allocations allowed) ----------------
__device__ float g_Wt[IN_DIM * WT_COLS];              // [k][o]: W^T | va | 0
__device__ float g_h[(size_t)N_MAX * OUT_DIM];        // projected features
__device__ float g_ssrc[N_MAX * NH];
__device__ float g_sdst[N_MAX * NH];
__device__ int   g_deg[N_MAX];
__device__ int   g_rowptr[N_MAX + 1];
__device__ int   g_wpos[N_MAX];
__device__ int   g_csr[E_MAX];
__device__ int   g_partials[128];

// ---------------- fast exp on FMA pipe ------------------------------------
__device__ __forceinline__ float fast_exp(float x) {
    float t = x * 1.4426950408889634f;
    float n = rintf(t);
    float u = t - n;
    float p = 1.33335581464e-3f;
    p = fmaf(p, u, 9.61812910763e-3f);
    p = fmaf(p, u, 5.55041086648e-2f);
    p = fmaf(p, u, 2.40226506959e-1f);
    p = fmaf(p, u, 6.93147180560e-1f);
    p = fmaf(p, u, 1.0f);
    int ni = (int)n;
    return __int_as_float(__float_as_int(p) + (ni << 23));
}

// ---------------- K_prep: build Wt|va|0, zero degree ---------------------
__global__ void k_prep(const float* __restrict__ W,
                       const float* __restrict__ a_src,
                       const float* __restrict__ a_dst, int n) {
    int idx = blockIdx.x * blockDim.x + threadIdx.x;
    if (idx < 8192) {
        int k = idx >> 6;
        int o = idx & 63;
        g_Wt[k * WT_COLS + o] = W[o * IN_DIM + k];
    } else if (idx < 9216) {
        int r = (idx - 8192) >> 7;        // 0..7
        int k = (idx - 8192) & 127;
        int hd = r & 3;
        const float* a = (r < 4) ? a_src : a_dst;
        float s = 0.f;
#pragma unroll
        for (int d = 0; d < DH; d++)
            s = fmaf(W[(hd * DH + d) * IN_DIM + k], a[hd * DH + d], s);
        g_Wt[k * WT_COLS + 64 + r] = s;
    } else if (idx < 10240) {
        int r = (idx - 9216) >> 7;        // 0..7
        int k = (idx - 9216) & 127;
        g_Wt[k * WT_COLS + 72 + r] = 0.f;
    } else if (idx - 10240 < n) {
        g_deg[idx - 10240] = 0;
    }
}

// ---------------- GEMM body: 64 rows x 80 cols, scalar FFMA --------------
// Thread (tx,ty): rows ty*4..+3, h cols tx*4..+3, score col 64+tx.
__device__ __forceinline__ void gemm_body(const float* __restrict__ x,
                                          int m0, int n) {
    __shared__ float xs[64][68];
    __shared__ float ws[64][84];

    const int t  = threadIdx.x;
    const int tx = t & 15;
    const int ty = t >> 4;

    float acc[4][4];
    float accs[4];
#pragma unroll
    for (int i = 0; i < 4; i++) {
#pragma unroll
        for (int j = 0; j < 4; j++) acc[i][j] = 0.f;
        accs[i] = 0.f;
    }

    for (int kk = 0; kk < IN_DIM; kk += 64) {
        // stage x: 64 rows x 16 float4
#pragma unroll
        for (int i = 0; i < 4; i++) {
            int f4 = t + i * 256;
            int r = f4 >> 4, c = f4 & 15;
            float4 v = make_float4(0.f, 0.f, 0.f, 0.f);
            if (m0 + r < n)
                v = *(const float4*)&x[(size_t)(m0 + r) * IN_DIM + kk + c * 4];
            *(float4*)&xs[r][c * 4] = v;
        }
        // stage Wt: 64 k-rows x 20 float4 (80 cols)
#pragma unroll
        for (int i = 0; i < 5; i++) {
            int f4 = t + i * 256;
            int k = f4 / 20, c = f4 % 20;
            *(float4*)&ws[k][c * 4] =
                *(const float4*)&g_Wt[(kk + k) * WT_COLS + c * 4];
        }
        __syncthreads();

#pragma unroll 8
        for (int k = 0; k < 64; k++) {
            float4 wv = *(float4*)&ws[k][tx * 4];
            float  sw = ws[k][64 + tx];
            float xv[4];
#pragma unroll
            for (int i = 0; i < 4; i++) xv[i] = xs[ty * 4 + i][k];
#pragma unroll
            for (int i = 0; i < 4; i++) {
                acc[i][0] = fmaf(xv[i], wv.x, acc[i][0]);
                acc[i][1] = fmaf(xv[i], wv.y, acc[i][1]);
                acc[i][2] = fmaf(xv[i], wv.z, acc[i][2]);
                acc[i][3] = fmaf(xv[i], wv.w, acc[i][3]);
                accs[i]   = fmaf(xv[i], sw,   accs[i]);
            }
        }
        __syncthreads();
    }

#pragma unroll
    for (int i = 0; i < 4; i++) {
        int row = m0 + ty * 4 + i;
        if (row < n) {
            float4 v = make_float4(acc[i][0], acc[i][1], acc[i][2], acc[i][3]);
            *(float4*)&g_h[(size_t)row * OUT_DIM + tx * 4] = v;
            if (tx < 4)      g_ssrc[row * NH + tx]       = accs[i];
            else if (tx < 8) g_sdst[row * NH + (tx - 4)] = accs[i];
        }
    }
}

// ---------------- K1: hist blocks + gemm part A --------------------------
__global__ __launch_bounds__(256) void k1_hist_gemm(const float* __restrict__ x,
                                                    const int* __restrict__ dst,
                                                    int n, int e) {
    if (blockIdx.x < HIST_BLOCKS) {
        const int stride = HIST_BLOCKS * 256;
        for (int i = blockIdx.x * 256 + threadIdx.x; i < e; i += stride)
            atomicAdd(&g_deg[__ldg(&dst[i])], 1);
        return;
    }
    gemm_body(x, (blockIdx.x - HIST_BLOCKS) * 64, n);
}

// ---------------- K2: reorder blocks + gemm part B -----------------------
__global__ __launch_bounds__(256) void k2_reord_gemm(const float* __restrict__ x,
                                                     const int* __restrict__ src,
                                                     const int* __restrict__ dst,
                                                     int n, int e, int m_base) {
    if (blockIdx.x < REORD_BLOCKS) {
        const int stride = REORD_BLOCKS * 256;
        for (int i = blockIdx.x * 256 + threadIdx.x; i < e; i += stride) {
            int d = __ldg(&dst[i]);
            int p = atomicAdd(&g_wpos[d], 1);
            g_csr[p] = __ldg(&src[i]);
        }
        return;
    }
    gemm_body(x, m_base + (blockIdx.x - REORD_BLOCKS) * 64, n);
}

// ---------------- K4: 3-step exclusive scan of degrees -------------------
__global__ void k_scan_a(int n) {
    __shared__ int warp_sums[32];
    int i = blockIdx.x * 1024 + threadIdx.x;
    int lane = threadIdx.x & 31, wid = threadIdx.x >> 5;
    int v = (i < n) ? g_deg[i] : 0;
    int s = v;
#pragma unroll
    for (int o = 1; o < 32; o <<= 1) {
        int t = __shfl_up_sync(0xFFFFFFFFu, s, o);
        if (lane >= o) s += t;
    }
    if (lane == 31) warp_sums[wid] = s;
    __syncthreads();
    if (wid == 0) {
        int wsv = warp_sums[lane];
#pragma unroll
        for (int o = 1; o < 32; o <<= 1) {
            int t = __shfl_up_sync(0xFFFFFFFFu, wsv, o);
            if (lane >= o) wsv += t;
        }
        warp_sums[lane] = wsv;
    }
    __syncthreads();
    int off = wid ? warp_sums[wid - 1] : 0;
    int incl = s + off;
    if (i < n) g_rowptr[i] = incl - v;
    if (threadIdx.x == 1023) g_partials[blockIdx.x] = incl;
}

__global__ void k_scan_b(int nb) {
    __shared__ int sm[4];
    int t = threadIdx.x;
    int lane = t & 31, wid = t >> 5;
    int v = (t < nb) ? g_partials[t] : 0;
    int s = v;
#pragma unroll
    for (int o = 1; o < 32; o <<= 1) {
        int x = __shfl_up_sync(0xFFFFFFFFu, s, o);
        if (lane >= o) s += x;
    }
    if (lane == 31) sm[wid] = s;
    __syncthreads();
    int off = 0;
    for (int k = 0; k < wid; k++) off += sm[k];
    g_partials[t] = s + off - v;
}

__global__ void k_scan_c(int n, int e) {
    int i = blockIdx.x * 1024 + threadIdx.x;
    if (i < n) {
        int r = g_rowptr[i] + g_partials[i >> 10];
        g_rowptr[i] = r;
        g_wpos[i]   = r;
    }
    if (i == 0) g_rowptr[n] = e;
}

// ---------------- K6: fused softmax + weighted aggregation ---------------
__global__ __launch_bounds__(256) void k_agg(float* __restrict__ out, int n) {
    int w = (blockIdx.x * blockDim.x + threadIdx.x) >> 5;
    if (w >= n) return;
    int lane = threadIdx.x & 31;
    int slot = lane >> 4;
    int q    = lane & 15;
    int hd   = q >> 2;

    int start = g_rowptr[w];
    int end   = g_rowptr[w + 1];
    float sdst = g_sdst[w * NH + hd];

    float4 acc = make_float4(0.f, 0.f, 0.f, 0.f);
    float ssum = 0.f;

    int j = start + slot;
    int src_cur = (j < end) ? __ldg(&g_csr[j]) : 0;
    for (; j < end; j += 2) {
        int jn = j + 2;
        int src_nxt = (jn < end) ? __ldg(&g_csr[jn]) : 0;   // prefetch
        int src = src_cur;
        float s = __ldg(&g_ssrc[src * NH + hd]) + sdst;
        float ev = (s > 0.f) ? s : 0.2f * s;       // leaky_relu(0.2)
        float p = fast_exp(ev);                    // unshifted exp: max cancels
        float4 hv = *(const float4*)&g_h[(size_t)src * OUT_DIM + q * 4];
        acc.x = fmaf(p, hv.x, acc.x);
        acc.y = fmaf(p, hv.y, acc.y);
        acc.z = fmaf(p, hv.z, acc.z);
        acc.w = fmaf(p, hv.w, acc.w);
        ssum += p;
        src_cur = src_nxt;
    }

    acc.x += __shfl_xor_sync(0xFFFFFFFFu, acc.x, 16);
    acc.y += __shfl_xor_sync(0xFFFFFFFFu, acc.y, 16);
    acc.z += __shfl_xor_sync(0xFFFFFFFFu, acc.z, 16);
    acc.w += __shfl_xor_sync(0xFFFFFFFFu, acc.w, 16);
    ssum  += __shfl_xor_sync(0xFFFFFFFFu, ssum, 16);

    if (slot == 0) {
        float inv = 1.f / fmaxf(ssum, 1e-9f);
        float4 o = make_float4(acc.x * inv, acc.y * inv, acc.z * inv, acc.w * inv);
        *(float4*)&out[(size_t)w * OUT_DIM + q * 4] = o;
    }
}

// ---------------- launch ---------------------------------------------------
extern "C" void kernel_launch(void* const* d_in, const int* in_sizes, int n_in,
                              void* d_out, int out_size) {
    const float* x     = (const float*)d_in[0];
    const float* W     = (const float*)d_in[1];
    const float* a_src = (const float*)d_in[2];
    const float* a_dst = (const float*)d_in[3];
    const int*   ei    = (const int*)d_in[4];

    int n = in_sizes[0] / IN_DIM;
    int e = in_sizes[4] / 2;
    const int* srcp = ei;
    const int* dstp = ei + e;
    float* out = (float*)d_out;

    int gemm_total = (n + 63) / 64;
    int ga = (gemm_total * 3) / 5;           // ~60% of rows in k1
    int gb = gemm_total - ga;
    int nb = (n + 1023) / 1024;

    k_prep       <<<(10240 + n + 255) / 256, 256>>>(W, a_src, a_dst, n);
    k1_hist_gemm <<<HIST_BLOCKS + ga, 256>>>(x, dstp, n, e);
    k_scan_a     <<<nb, 1024>>>(n);
    k_scan_b     <<<1, 128>>>(nb);
    k_scan_c     <<<nb, 1024>>>(n, e);
    k2_reord_gemm<<<REORD_BLOCKS + gb, 256>>>(x, srcp, dstp, n, e, ga * 64);
    k_agg        <<<(n + 7) / 8, 256>>>(out, n);
}

// round 8
// speedup vs baseline: 1.1458x; 1.0147x over previous
#include <cuda_runtime.h>
#include <cuda_fp16.h>
#include <stdint.h>

#define IN_DIM 128
#define OUT_DIM 64
#define NH 4
#define DH 16
#define N_MAX 100000
#define E_MAX 1600000

#define WT_COLS 80          // 64 h cols + 8 score cols + 8 zero pad
#define HIST_BLOCKS 128
#define REORD_BLOCKS 128

// ---------------- device scratch (no allocations allowed) ----------------
__device__ float  g_Wt[IN_DIM * WT_COLS];             // [k][o]: W^T | va | 0
__device__ __half g_h16[(size_t)N_MAX * OUT_DIM];     // projected features (fp16)
__device__ float  g_ssrc[N_MAX * NH];
__device__ float  g_sdst[N_MAX * NH];
__device__ int    g_deg[N_MAX];
__device__ int    g_rowptr[N_MAX + 1];
__device__ int    g_wpos[N_MAX];
__device__ int    g_csr[E_MAX];
__device__ int    g_bsum[128];         // per-block totals (scan)
__device__ int    g_boff[128];         // per-block exclusive offsets
__device__ int    g_count;             // scan arrival ticket
__device__ int    g_flag;              // scan offsets-ready flag

// ---------------- fast exp on FMA pipe ------------------------------------
__device__ __forceinline__ float fast_exp(float x) {
    float t = x * 1.4426950408889634f;
    float n = rintf(t);
    float u = t - n;
    float p = 1.33335581464e-3f;
    p = fmaf(p, u, 9.61812910763e-3f);
    p = fmaf(p, u, 5.55041086648e-2f);
    p = fmaf(p, u, 2.40226506959e-1f);
    p = fmaf(p, u, 6.93147180560e-1f);
    p = fmaf(p, u, 1.0f);
    int ni = (int)n;
    return __int_as_float(__float_as_int(p) + (ni << 23));
}

// ---------------- K_prep: build Wt|va|0, zero degree, reset scan sync ----
__global__ void k_prep(const float* __restrict__ W,
                       const float* __restrict__ a_src,
                       const float* __restrict__ a_dst, int n) {
    int idx = blockIdx.x * blockDim.x + threadIdx.x;
    if (idx == 0) { g_count = 0; g_flag = 0; }
    if (idx < 8192) {
        int k = idx >> 6;
        int o = idx & 63;
        g_Wt[k * WT_COLS + o] = W[o * IN_DIM + k];
    } else if (idx < 9216) {
        int r = (idx - 8192) >> 7;        // 0..7
        int k = (idx - 8192) & 127;
        int hd = r & 3;
        const float* a = (r < 4) ? a_src : a_dst;
        float s = 0.f;
#pragma unroll
        for (int d = 0; d < DH; d++)
            s = fmaf(W[(hd * DH + d) * IN_DIM + k], a[hd * DH + d], s);
        g_Wt[k * WT_COLS + 64 + r] = s;
    } else if (idx < 10240) {
        int r = (idx - 9216) >> 7;        // 0..7
        int k = (idx - 9216) & 127;
        g_Wt[k * WT_COLS + 72 + r] = 0.f;
    } else if (idx - 10240 < n) {
        g_deg[idx - 10240] = 0;
    }
}

// ---------------- GEMM body: 64 rows x 80 cols, scalar FFMA --------------
// Thread (tx,ty): rows ty*4..+3, h cols tx*4..+3, score col 64+tx.
// h written as fp16 (sole consumer is the agg gather).
__device__ __forceinline__ void gemm_body(const float* __restrict__ x,
                                          int m0, int n) {
    __shared__ float xs[64][68];
    __shared__ float ws[64][84];

    const int t  = threadIdx.x;
    const int tx = t & 15;
    const int ty = t >> 4;

    float acc[4][4];
    float accs[4];
#pragma unroll
    for (int i = 0; i < 4; i++) {
#pragma unroll
        for (int j = 0; j < 4; j++) acc[i][j] = 0.f;
        accs[i] = 0.f;
    }

    for (int kk = 0; kk < IN_DIM; kk += 64) {
#pragma unroll
        for (int i = 0; i < 4; i++) {
            int f4 = t + i * 256;
            int r = f4 >> 4, c = f4 & 15;
            float4 v = make_float4(0.f, 0.f, 0.f, 0.f);
            if (m0 + r < n)
                v = *(const float4*)&x[(size_t)(m0 + r) * IN_DIM + kk + c * 4];
            *(float4*)&xs[r][c * 4] = v;
        }
#pragma unroll
        for (int i = 0; i < 5; i++) {
            int f4 = t + i * 256;
            int k = f4 / 20, c = f4 % 20;
            *(float4*)&ws[k][c * 4] =
                *(const float4*)&g_Wt[(kk + k) * WT_COLS + c * 4];
        }
        __syncthreads();

#pragma unroll 8
        for (int k = 0; k < 64; k++) {
            float4 wv = *(float4*)&ws[k][tx * 4];
            float  sw = ws[k][64 + tx];
            float xv[4];
#pragma unroll
            for (int i = 0; i < 4; i++) xv[i] = xs[ty * 4 + i][k];
#pragma unroll
            for (int i = 0; i < 4; i++) {
                acc[i][0] = fmaf(xv[i], wv.x, acc[i][0]);
                acc[i][1] = fmaf(xv[i], wv.y, acc[i][1]);
                acc[i][2] = fmaf(xv[i], wv.z, acc[i][2]);
                acc[i][3] = fmaf(xv[i], wv.w, acc[i][3]);
                accs[i]   = fmaf(xv[i], sw,   accs[i]);
            }
        }
        __syncthreads();
    }

#pragma unroll
    for (int i = 0; i < 4; i++) {
        int row = m0 + ty * 4 + i;
        if (row < n) {
            union { __half2 h[2]; uint2 u; } cv;
            cv.h[0] = __floats2half2_rn(acc[i][0], acc[i][1]);
            cv.h[1] = __floats2half2_rn(acc[i][2], acc[i][3]);
            *(uint2*)&g_h16[(size_t)row * OUT_DIM + tx * 4] = cv.u;
            if (tx < 4)      g_ssrc[row * NH + tx]       = accs[i];
            else if (tx < 8) g_sdst[row * NH + (tx - 4)] = accs[i];
        }
    }
}

// ---------------- K1: hist blocks + gemm part A --------------------------
__global__ __launch_bounds__(256) void k1_hist_gemm(const float* __restrict__ x,
                                                    const int* __restrict__ dst,
                                                    int n, int e) {
    if (blockIdx.x < HIST_BLOCKS) {
        const int stride = HIST_BLOCKS * 256;
        for (int i = blockIdx.x * 256 + threadIdx.x; i < e; i += stride)
            atomicAdd(&g_deg[__ldg(&dst[i])], 1);
        return;
    }
    gemm_body(x, (blockIdx.x - HIST_BLOCKS) * 64, n);
}

// ---------------- K_scan: single-kernel exclusive scan (one wave) --------
// grid = ceil(n/1024) <= 98 < 148 SMs -> all blocks co-resident, flat sync.
__global__ __launch_bounds__(1024) void k_scan(int n, int e) {
    __shared__ int warp_sums[32];
    __shared__ int sh_last;
    __shared__ int sh_total;

    int b = blockIdx.x, t = threadIdx.x;
    int i = b * 1024 + t;
    int lane = t & 31, wid = t >> 5;

    int v = (i < n) ? g_deg[i] : 0;
    int s = v;
#pragma unroll
    for (int o = 1; o < 32; o <<= 1) {
        int u = __shfl_up_sync(0xFFFFFFFFu, s, o);
        if (lane >= o) s += u;
    }
    if (lane == 31) warp_sums[wid] = s;
    __syncthreads();
    if (wid == 0) {
        int wsv = warp_sums[lane];
#pragma unroll
        for (int o = 1; o < 32; o <<= 1) {
            int u = __shfl_up_sync(0xFFFFFFFFu, wsv, o);
            if (lane >= o) wsv += u;
        }
        warp_sums[lane] = wsv;
    }
    __syncthreads();
    int woff = wid ? warp_sums[wid - 1] : 0;
    int incl = s + woff;
    int lexcl = incl - v;                 // local exclusive prefix

    if (t == 1023) sh_total = incl;
    __syncthreads();
    if (t == 0) {
        g_bsum[b] = sh_total;
        __threadfence();
        int old = atomicAdd(&g_count, 1);
        sh_last = (old == gridDim.x - 1) ? 1 : 0;
    }
    __syncthreads();

    if (sh_last) {
        if (t < 32) {                     // one warp scans <=128 block totals
            int base = t * 4;
            int vals[4];
#pragma unroll
            for (int j = 0; j < 4; j++)
                vals[j] = (base + j < (int)gridDim.x) ? g_bsum[base + j] : 0;
            int loc = vals[0] + vals[1] + vals[2] + vals[3];
            int sc = loc;
#pragma unroll
            for (int o = 1; o < 32; o <<= 1) {
                int u = __shfl_up_sync(0xFFFFFFFFu, sc, o);
                if (lane >= o) sc += u;
            }
            int run = sc - loc;           // exclusive across groups of 4
#pragma unroll
            for (int j = 0; j < 4; j++) {
                if (base + j < (int)gridDim.x) g_boff[base + j] = run;
                run += vals[j];
            }
            __threadfence();
            if (t == 0) atomicExch(&g_flag, 1);
        }
    }
    if (t == 0) {
        while (atomicAdd(&g_flag, 0) == 0) { __nanosleep(100); }
    }
    __syncthreads();

    int boff = g_boff[b];
    if (i < n) {
        int r = lexcl + boff;
        g_rowptr[i] = r;
        g_wpos[i]   = r;
    }
    if (i == 0) g_rowptr[n] = e;
}

// ---------------- K2: reorder blocks + gemm part B -----------------------
__global__ __launch_bounds__(256) void k2_reord_gemm(const float* __restrict__ x,
                                                     const int* __restrict__ src,
                                                     const int* __restrict__ dst,
                                                     int n, int e, int m_base) {
    if (blockIdx.x < REORD_BLOCKS) {
        const int stride = REORD_BLOCKS * 256;
        for (int i = blockIdx.x * 256 + threadIdx.x; i < e; i += stride) {
            int d = __ldg(&dst[i]);
            int p = atomicAdd(&g_wpos[d], 1);
            g_csr[p] = __ldg(&src[i]);
        }
        return;
    }
    gemm_body(x, m_base + (blockIdx.x - REORD_BLOCKS) * 64, n);
}

// ---------------- K_agg: fused softmax + fp16-gather aggregation ---------
// One warp per dst node, 16 lanes per edge (lane q: cols 4q..4q+3, 8 bytes
// fp16), 2 edges in flight, CSR-index prefetch. fp32 accumulation.
__global__ __launch_bounds__(256) void k_agg(float* __restrict__ out, int n) {
    int w = (blockIdx.x * blockDim.x + threadIdx.x) >> 5;
    if (w >= n) return;
    int lane = threadIdx.x & 31;
    int slot = lane >> 4;
    int q    = lane & 15;
    int hd   = q >> 2;

    int start = g_rowptr[w];
    int end   = g_rowptr[w + 1];
    float sdst = g_sdst[w * NH + hd];

    float4 acc = make_float4(0.f, 0.f, 0.f, 0.f);
    float ssum = 0.f;

    int j = start + slot;
    int src_cur = (j < end) ? __ldg(&g_csr[j]) : 0;
    for (; j < end; j += 2) {
        int jn = j + 2;
        int src_nxt = (jn < end) ? __ldg(&g_csr[jn]) : 0;   // prefetch
        int src = src_cur;
        float s = __ldg(&g_ssrc[src * NH + hd]) + sdst;
        float ev = (s > 0.f) ? s : 0.2f * s;       // leaky_relu(0.2)
        float p = fast_exp(ev);                    // unshifted exp: max cancels

        union { uint2 u; __half2 h[2]; } cv;
        cv.u = *(const uint2*)&g_h16[(size_t)src * OUT_DIM + q * 4];
        float2 f0 = __half22float2(cv.h[0]);
        float2 f1 = __half22float2(cv.h[1]);

        acc.x = fmaf(p, f0.x, acc.x);
        acc.y = fmaf(p, f0.y, acc.y);
        acc.z = fmaf(p, f1.x, acc.z);
        acc.w = fmaf(p, f1.y, acc.w);
        ssum += p;
        src_cur = src_nxt;
    }

    acc.x += __shfl_xor_sync(0xFFFFFFFFu, acc.x, 16);
    acc.y += __shfl_xor_sync(0xFFFFFFFFu, acc.y, 16);
    acc.z += __shfl_xor_sync(0xFFFFFFFFu, acc.z, 16);
    acc.w += __shfl_xor_sync(0xFFFFFFFFu, acc.w, 16);
    ssum  += __shfl_xor_sync(0xFFFFFFFFu, ssum, 16);

    if (slot == 0) {
        float inv = 1.f / fmaxf(ssum, 1e-9f);
        float4 o = make_float4(acc.x * inv, acc.y * inv, acc.z * inv, acc.w * inv);
        *(float4*)&out[(size_t)w * OUT_DIM + q * 4] = o;
    }
}

// ---------------- launch ---------------------------------------------------
extern "C" void kernel_launch(void* const* d_in, const int* in_sizes, int n_in,
                              void* d_out, int out_size) {
    const float* x     = (const float*)d_in[0];
    const float* W     = (const float*)d_in[1];
    const float* a_src = (const float*)d_in[2];
    const float* a_dst = (const float*)d_in[3];
    const int*   ei    = (const int*)d_in[4];

    int n = in_sizes[0] / IN_DIM;
    int e = in_sizes[4] / 2;
    const int* srcp = ei;
    const int* dstp = ei + e;
    float* out = (float*)d_out;

    int gemm_total = (n + 63) / 64;
    int ga = (gemm_total * 3) / 5;           // ~60% of rows in k1
    int gb = gemm_total - ga;
    int nb = (n + 1023) / 1024;              // <=98 blocks, one wave

    k_prep       <<<(10240 + n + 255) / 256, 256>>>(W, a_src, a_dst, n);
    k1_hist_gemm <<<HIST_BLOCKS + ga, 256>>>(x, dstp, n, e);
    k_scan       <<<nb, 1024>>>(n, e);
    k2_reord_gemm<<<REORD_BLOCKS + gb, 256>>>(x, srcp, dstp, n, e, ga * 64);
    k_agg        <<<(n + 7) / 8, 256>>>(out, n);
}